// round 13
// baseline (speedup 1.0000x reference)
#include <cuda_runtime.h>
#include <cuda_bf16.h>
#include <cstdint>
#include <cstddef>

// Problem constants: B=8, T=2048, D=1024, KQ=128, topk=8
#define Bz   8
#define Tz   2048
#define Dz   1024
#define KQz  128
#define TOPK 8
#define BT   (Bz * Tz)          // 16384 rows
#define SIM_SCALE 0.08838834764831843f   // 1/sqrt(128)

typedef unsigned long long ull;

// Scratch (device globals: no allocation allowed in kernel_launch)
__device__ float g_q[BT * KQz];      // 8 MB
__device__ float g_k[BT * KQz];      // 8 MB
__device__ int   g_idx[BT * TOPK];   // routed indices for gather

// ---------------------------------------------------------------------------
// f32x2 packed-FMA helpers (FFMA2: 2 fp32 FMAs per instruction)
// ---------------------------------------------------------------------------
__device__ __forceinline__ ull pack2(float a, float b) {
    ull r;
    asm("mov.b64 %0, {%1, %2};" : "=l"(r)
        : "r"(__float_as_uint(a)), "r"(__float_as_uint(b)));
    return r;
}
__device__ __forceinline__ void unpack2(ull v, float& a, float& b) {
    unsigned int lo, hi;
    asm("mov.b64 {%0, %1}, %2;" : "=r"(lo), "=r"(hi) : "l"(v));
    a = __uint_as_float(lo);
    b = __uint_as_float(hi);
}
__device__ __forceinline__ void fma2(ull& d, ull a, ull b) {
    asm("fma.rn.f32x2 %0, %1, %2, %0;" : "+l"(d) : "l"(a), "l"(b));
}
__device__ __forceinline__ float neg_inf() { return __int_as_float(0xff800000); }

// ---------------------------------------------------------------------------
// Kernel 1 (UNCHANGED — ~measured fp32 roofline): projection GEMM.
// blockIdx.y = 0 -> Q (Wq,bq), 1 -> K (Wk,bk). 128x128 CTA tile, 8x8/thread.
// ---------------------------------------------------------------------------
__global__ __launch_bounds__(256)
void qk2_kernel(const float* __restrict__ x,
                const float* __restrict__ Wq, const float* __restrict__ bq,
                const float* __restrict__ Wk, const float* __restrict__ bk) {
    __shared__ float xs[32 * 132];   // [k][row], stride 132
    __shared__ float ws[32 * 132];   // [k][col], stride 132

    const float* W    = blockIdx.y ? Wk : Wq;
    const float* bias = blockIdx.y ? bk : bq;
    float* outp       = blockIdx.y ? g_k : g_q;

    const int tid  = threadIdx.x;
    const int tx   = tid & 15;
    const int ty   = tid >> 4;
    const int row0 = blockIdx.x * 128;

    int c4a[4], ra[4];
#pragma unroll
    for (int i = 0; i < 4; i++) {
        int s = tid + i * 256;
        c4a[i] = (s & 1) + (((s >> 5) & 3) << 1);
        ra[i]  = ((s >> 1) & 15) + ((s >> 7) << 4);
    }

    ull acc[8][4];
#pragma unroll
    for (int i = 0; i < 8; i++)
#pragma unroll
        for (int j = 0; j < 4; j++) acc[i][j] = 0ull;

    float4 px[4], pw[4];
#pragma unroll
    for (int i = 0; i < 4; i++) {
        px[i] = *(const float4*)&x[(size_t)(row0 + ra[i]) * Dz + c4a[i] * 4];
        pw[i] = *(const float4*)&W[(size_t)ra[i] * Dz + c4a[i] * 4];
    }

    for (int kb = 0; kb < 32; kb++) {
#pragma unroll
        for (int i = 0; i < 4; i++) {
            int kbase = c4a[i] * 4, r = ra[i];
            xs[(kbase + 0) * 132 + r] = px[i].x; xs[(kbase + 1) * 132 + r] = px[i].y;
            xs[(kbase + 2) * 132 + r] = px[i].z; xs[(kbase + 3) * 132 + r] = px[i].w;
            ws[(kbase + 0) * 132 + r] = pw[i].x; ws[(kbase + 1) * 132 + r] = pw[i].y;
            ws[(kbase + 2) * 132 + r] = pw[i].z; ws[(kbase + 3) * 132 + r] = pw[i].w;
        }
        __syncthreads();

        if (kb < 31) {
            int koff = (kb + 1) * 32;
#pragma unroll
            for (int i = 0; i < 4; i++) {
                px[i] = *(const float4*)&x[(size_t)(row0 + ra[i]) * Dz + koff + c4a[i] * 4];
                pw[i] = *(const float4*)&W[(size_t)ra[i] * Dz + koff + c4a[i] * 4];
            }
        }

#pragma unroll 8
        for (int kk = 0; kk < 32; kk++) {
            float4 a0 = *(const float4*)&xs[kk * 132 + ty * 8];
            float4 a1 = *(const float4*)&xs[kk * 132 + ty * 8 + 4];
            ull ap[8] = { pack2(a0.x, a0.x), pack2(a0.y, a0.y),
                          pack2(a0.z, a0.z), pack2(a0.w, a0.w),
                          pack2(a1.x, a1.x), pack2(a1.y, a1.y),
                          pack2(a1.z, a1.z), pack2(a1.w, a1.w) };
            ulonglong2 b0 = *(const ulonglong2*)&ws[kk * 132 + tx * 8];
            ulonglong2 b1 = *(const ulonglong2*)&ws[kk * 132 + tx * 8 + 4];
            ull bp[4] = { b0.x, b0.y, b1.x, b1.y };
#pragma unroll
            for (int i = 0; i < 8; i++)
#pragma unroll
                for (int j = 0; j < 4; j++) fma2(acc[i][j], ap[i], bp[j]);
        }
        __syncthreads();
    }

    float bv[8];
#pragma unroll
    for (int j = 0; j < 8; j++) bv[j] = bias[tx * 8 + j];

#pragma unroll
    for (int i = 0; i < 8; i++) {
        float o[8];
#pragma unroll
        for (int j = 0; j < 4; j++) unpack2(acc[i][j], o[2 * j], o[2 * j + 1]);
        int grow = row0 + ty * 8 + i;
        float4 s0 = { o[0] + bv[0], o[1] + bv[1], o[2] + bv[2], o[3] + bv[3] };
        float4 s1 = { o[4] + bv[4], o[5] + bv[5], o[6] + bv[6], o[7] + bv[7] };
        *(float4*)&outp[(size_t)grow * KQz + tx * 8]     = s0;
        *(float4*)&outp[(size_t)grow * KQz + tx * 8 + 4] = s1;
    }
}

// ---------------------------------------------------------------------------
// top-8 insertion (sorted desc; ascending-index feed => stable ties)
// ---------------------------------------------------------------------------
__device__ __forceinline__ void topk_insert(float v, int i,
                                            float (&tv)[8], int (&ti)[8]) {
    if (v > tv[7]) {
        float pv = v; int pi = i;
#pragma unroll
        for (int p = 0; p < 8; p++) {
            if (pv > tv[p]) {
                float t = tv[p]; int u = ti[p];
                tv[p] = pv; ti[p] = pi;
                pv = t; pi = u;
            }
        }
    }
}

// ---------------------------------------------------------------------------
// Kernel 2: sim = (Q @ K^T) * scale, fused streaming exact top-8.
// CTA: 128 q-rows x 128-key HALF-chunks (16 halves), 512 threads, 4x8 thread
// tiles. K halves double-buffered; the next half's LDG (d=0..7) and scattered
// STS (d=64..95) are interleaved INTO the FFMA2 d-loop -> load latency hidden
// behind the FFMA2-pipe-bound GEMM. Stage+scan per half as before; 4-way
// merge of per-quarter lists at the end. Arithmetic order identical.
// ---------------------------------------------------------------------------
#define QST 132
#define KST 132
#define K2_SMEM ((128 * QST * 3) * 4)     // Qs + 2 half-buffers = 202752 B

#define GEMM_STEP(dd)                                                         \
    {                                                                         \
        float4 a = *(const float4*)&Qs[(dd) * QST + ty * 4];                  \
        ull ap[4] = { pack2(a.x, a.x), pack2(a.y, a.y),                       \
                      pack2(a.z, a.z), pack2(a.w, a.w) };                     \
        ulonglong2 b0 = *(const ulonglong2*)&Kc[(dd) * KST + tx * 8];         \
        ulonglong2 b1 = *(const ulonglong2*)&Kc[(dd) * KST + tx * 8 + 4];     \
        ull bp[4] = { b0.x, b0.y, b1.x, b1.y };                               \
        _Pragma("unroll")                                                     \
        for (int ii = 0; ii < 4; ii++)                                        \
            _Pragma("unroll")                                                 \
            for (int jj = 0; jj < 4; jj++) fma2(acc[ii][jj], ap[ii], bp[jj]); \
    }

__global__ __launch_bounds__(512)
void sim_topk_kernel(float* __restrict__ out_idx, float* __restrict__ out_sim) {
    extern __shared__ float sm[];
    float* Qs = sm;                        // [128 d][132] (128 rows + pad)
    float* Kb0 = sm + 128 * QST;           // half buffer 0: [128 d][132]
    float* Kb1 = sm + 2 * 128 * QST;       // half buffer 1

    const int tid  = threadIdx.x;
    const int tx   = tid & 15;             // 8 keys each -> 128 keys
    const int ty   = tid >> 4;             // 4 rows each -> 128 rows (0..31)
    const int row0 = blockIdx.x * 128;
    const int b    = row0 >> 11;
    const int key0 = b * Tz;

    // loader decomposition (8 float4/thread, conflict-free scattered STS)
    int lc4[8], lt[8];
#pragma unroll
    for (int j = 0; j < 8; j++) {
        int s = tid + j * 512;
        lc4[j] = (s & 1) + (((s >> 5) & 15) << 1);    // dim group [0,32)
        lt[j]  = ((s >> 1) & 15) + ((s >> 9) << 4);   // key/row  [0,128)
    }

    // prologue: Q tile (transposed) + K half 0 into Kb0
#pragma unroll
    for (int j = 0; j < 8; j++) {
        float4 v = *(const float4*)&g_q[(size_t)(row0 + lt[j]) * KQz + lc4[j] * 4];
        Qs[(lc4[j] * 4 + 0) * QST + lt[j]] = v.x;
        Qs[(lc4[j] * 4 + 1) * QST + lt[j]] = v.y;
        Qs[(lc4[j] * 4 + 2) * QST + lt[j]] = v.z;
        Qs[(lc4[j] * 4 + 3) * QST + lt[j]] = v.w;
    }
#pragma unroll
    for (int j = 0; j < 8; j++) {
        float4 v = *(const float4*)&g_k[(size_t)(key0 + lt[j]) * KQz + lc4[j] * 4];
        Kb0[(lc4[j] * 4 + 0) * KST + lt[j]] = v.x;
        Kb0[(lc4[j] * 4 + 1) * KST + lt[j]] = v.y;
        Kb0[(lc4[j] * 4 + 2) * KST + lt[j]] = v.z;
        Kb0[(lc4[j] * 4 + 3) * KST + lt[j]] = v.w;
    }

    float tv[8]; int ti[8];
#pragma unroll
    for (int p = 0; p < 8; p++) { tv[p] = neg_inf(); ti[p] = 0x7fffffff; }

    const int srow  = tid >> 2;            // scan row [0,128)
    const int squad = tid & 3;             // scan quarter: 32 keys

#pragma unroll 1
    for (int h = 0; h < 16; h++) {
        float* Kc = (h & 1) ? Kb1 : Kb0;
        float* Kn = (h & 1) ? Kb0 : Kb1;
        const bool doload = h < 15;
        const float* gsrc = &g_k[(size_t)(key0 + ((h + 1) & 15) * 128) * KQz];

        __syncthreads();   // half h loaded; prev scan done (Kn free)

        ull acc[4][4];
#pragma unroll
        for (int i = 0; i < 4; i++)
#pragma unroll
            for (int j = 0; j < 4; j++) acc[i][j] = 0ull;

        float4 pf[8];
        // segment A: d = 0..7, one prefetch LDG per iter
#pragma unroll
        for (int d = 0; d < 8; d++) {
            GEMM_STEP(d);
            if (doload)
                pf[d] = *(const float4*)&gsrc[(size_t)lt[d] * KQz + lc4[d] * 4];
        }
        // segment B: pure GEMM
#pragma unroll 8
        for (int d = 8; d < 64; d++) GEMM_STEP(d);
        // segment C: d = 64..95, one scattered STS.32 per iter (fully unrolled
        // so pf[] indices stay compile-time -> registers)
#pragma unroll
        for (int d = 64; d < 96; d++) {
            GEMM_STEP(d);
            if (doload) {
                const int j  = d - 64;
                const int f4 = j >> 2, cc = j & 3;
                const float* pfp = (const float*)&pf[f4];
                Kn[(lc4[f4] * 4 + cc) * KST + lt[f4]] = pfp[cc];
            }
        }
        // segment D: pure GEMM
#pragma unroll 8
        for (int d = 96; d < 128; d++) GEMM_STEP(d);

        __syncthreads();   // acc final; Kc reads done; Kn fully stored

        // stage scaled sim tile into Kc: St[row][key], stride KST
#pragma unroll
        for (int i = 0; i < 4; i++) {
            float o[8];
#pragma unroll
            for (int j = 0; j < 4; j++) unpack2(acc[i][j], o[2 * j], o[2 * j + 1]);
            int r = ty * 4 + i;
            float4 s0 = { o[0] * SIM_SCALE, o[1] * SIM_SCALE,
                          o[2] * SIM_SCALE, o[3] * SIM_SCALE };
            float4 s1 = { o[4] * SIM_SCALE, o[5] * SIM_SCALE,
                          o[6] * SIM_SCALE, o[7] * SIM_SCALE };
            *(float4*)&Kc[r * KST + tx * 8]     = s0;
            *(float4*)&Kc[r * KST + tx * 8 + 4] = s1;
        }
        __syncthreads();

        // scan: 4 threads/row, 32 keys each, group-max prefilter, asc index
        {
            const float* sp = &Kc[srow * KST + squad * 32];
            int kbase = h * 128 + squad * 32;
#pragma unroll
            for (int q = 0; q < 8; q++) {
                float4 v = *(const float4*)&sp[q * 4];
                float m = fmaxf(fmaxf(v.x, v.y), fmaxf(v.z, v.w));
                if (m > tv[7]) {
                    topk_insert(v.x, kbase + q * 4 + 0, tv, ti);
                    topk_insert(v.y, kbase + q * 4 + 1, tv, ti);
                    topk_insert(v.z, kbase + q * 4 + 2, tv, ti);
                    topk_insert(v.w, kbase + q * 4 + 3, tv, ti);
                }
            }
        }
        // no trailing sync: next iteration's leading sync orders scan vs reuse
    }
    __syncthreads();

    // 4-way merge of per-quarter sorted lists (dump into Qs region, now free)
    float* sv = Qs;                         // [128][4][8] values
    int*   si = (int*)(Qs + 4096);          // [128][4][8] indices
#pragma unroll
    for (int p = 0; p < 8; p++) {
        sv[(srow * 4 + squad) * 8 + p] = tv[p];
        si[(srow * 4 + squad) * 8 + p] = ti[p];
    }
    __syncthreads();

    if (tid < 128) {
        const float* v4 = &sv[tid * 32];
        const int*   i4 = &si[tid * 32];
        int p0 = 0, p1 = 0, p2 = 0, p3 = 0;
        int grow = row0 + tid;
#pragma unroll
        for (int r = 0; r < 8; r++) {
            float b0 = (p0 < 8) ? v4[p0]      : neg_inf();
            float b1 = (p1 < 8) ? v4[8 + p1]  : neg_inf();
            float b2 = (p2 < 8) ? v4[16 + p2] : neg_inf();
            float b3 = (p3 < 8) ? v4[24 + p3] : neg_inf();
            int   j0 = (p0 < 8) ? i4[p0]      : 0x7fffffff;
            int   j1 = (p1 < 8) ? i4[8 + p1]  : 0x7fffffff;
            int   j2 = (p2 < 8) ? i4[16 + p2] : 0x7fffffff;
            int   j3 = (p3 < 8) ? i4[24 + p3] : 0x7fffffff;
            float bv = b0; int bj = j0; int sel = 0;
            if (b1 > bv || (b1 == bv && j1 < bj)) { bv = b1; bj = j1; sel = 1; }
            if (b2 > bv || (b2 == bv && j2 < bj)) { bv = b2; bj = j2; sel = 2; }
            if (b3 > bv || (b3 == bv && j3 < bj)) { bv = b3; bj = j3; sel = 3; }
            if      (sel == 0) p0++;
            else if (sel == 1) p1++;
            else if (sel == 2) p2++;
            else               p3++;
            out_idx[(size_t)grow * TOPK + r] = (float)bj;
            out_sim[(size_t)grow * TOPK + r] = bv;
            g_idx [(size_t)grow * TOPK + r] = bj;
        }
    }
}

// ---------------------------------------------------------------------------
// Kernel 3: gather routed tokens. One CTA per query row; warp w copies pick w.
// ---------------------------------------------------------------------------
__global__ __launch_bounds__(256)
void gather_kernel(const float* __restrict__ x, float* __restrict__ out) {
    const int row  = blockIdx.x;
    const int w    = threadIdx.x >> 5;
    const int lane = threadIdx.x & 31;
    const int job  = row * TOPK + w;
    const int b    = row >> 11;
    const int idx  = g_idx[job];
    const float4* src = (const float4*)(x + (size_t)(b * Tz + idx) * Dz);
    float4* dst = (float4*)(out + (size_t)job * Dz);
#pragma unroll
    for (int j = 0; j < 8; j++) __stcs(&dst[j * 32 + lane], src[j * 32 + lane]);
}

// ---------------------------------------------------------------------------
extern "C" void kernel_launch(void* const* d_in, const int* in_sizes, int n_in,
                              void* d_out, int out_size) {
    const float* x  = (const float*)d_in[0];
    const float* Wq = (const float*)d_in[1];
    const float* bq = (const float*)d_in[2];
    const float* Wk = (const float*)d_in[3];
    const float* bk = (const float*)d_in[4];

    float* out      = (float*)d_out;
    float* out_g    = out;                                   // [B,T,8,D]
    float* out_idx  = out + (size_t)BT * TOPK * Dz;          // [B,T,8] as float
    float* out_sim  = out_idx + (size_t)BT * TOPK;           // [B,T,8]

    cudaFuncSetAttribute(sim_topk_kernel,
                         cudaFuncAttributeMaxDynamicSharedMemorySize, K2_SMEM);

    qk2_kernel<<<dim3(BT / 128, 2), 256>>>(x, Wq, bq, Wk, bk);
    sim_topk_kernel<<<BT / 128, 512, K2_SMEM>>>(out_idx, out_sim);
    gather_kernel<<<BT, 256>>>(x, out_g);
}

// round 14
// speedup vs baseline: 1.1479x; 1.1479x over previous
#include <cuda_runtime.h>
#include <cuda_bf16.h>
#include <cstdint>
#include <cstddef>

// Problem constants: B=8, T=2048, D=1024, KQ=128, topk=8
#define Bz   8
#define Tz   2048
#define Dz   1024
#define KQz  128
#define TOPK 8
#define BT   (Bz * Tz)          // 16384 rows
#define SIM_SCALE 0.08838834764831843f   // 1/sqrt(128)

typedef unsigned long long ull;

// Scratch (device globals: no allocation allowed in kernel_launch)
__device__ float g_q[BT * KQz];      // 8 MB
__device__ float g_k[BT * KQz];      // 8 MB

// ---------------------------------------------------------------------------
// f32x2 packed-FMA helpers (FFMA2: 2 fp32 FMAs per instruction)
// ---------------------------------------------------------------------------
__device__ __forceinline__ ull pack2(float a, float b) {
    ull r;
    asm("mov.b64 %0, {%1, %2};" : "=l"(r)
        : "r"(__float_as_uint(a)), "r"(__float_as_uint(b)));
    return r;
}
__device__ __forceinline__ void unpack2(ull v, float& a, float& b) {
    unsigned int lo, hi;
    asm("mov.b64 {%0, %1}, %2;" : "=r"(lo), "=r"(hi) : "l"(v));
    a = __uint_as_float(lo);
    b = __uint_as_float(hi);
}
__device__ __forceinline__ void fma2(ull& d, ull a, ull b) {
    asm("fma.rn.f32x2 %0, %1, %2, %0;" : "+l"(d) : "l"(a), "l"(b));
}
__device__ __forceinline__ float neg_inf() { return __int_as_float(0xff800000); }

// ---------------------------------------------------------------------------
// Kernel 1 (UNCHANGED — ~measured fp32 roofline): projection GEMM.
// blockIdx.y = 0 -> Q (Wq,bq), 1 -> K (Wk,bk). 128x128 CTA tile, 8x8/thread.
// ---------------------------------------------------------------------------
__global__ __launch_bounds__(256)
void qk2_kernel(const float* __restrict__ x,
                const float* __restrict__ Wq, const float* __restrict__ bq,
                const float* __restrict__ Wk, const float* __restrict__ bk) {
    __shared__ float xs[32 * 132];   // [k][row], stride 132
    __shared__ float ws[32 * 132];   // [k][col], stride 132

    const float* W    = blockIdx.y ? Wk : Wq;
    const float* bias = blockIdx.y ? bk : bq;
    float* outp       = blockIdx.y ? g_k : g_q;

    const int tid  = threadIdx.x;
    const int tx   = tid & 15;
    const int ty   = tid >> 4;
    const int row0 = blockIdx.x * 128;

    int c4a[4], ra[4];
#pragma unroll
    for (int i = 0; i < 4; i++) {
        int s = tid + i * 256;
        c4a[i] = (s & 1) + (((s >> 5) & 3) << 1);
        ra[i]  = ((s >> 1) & 15) + ((s >> 7) << 4);
    }

    ull acc[8][4];
#pragma unroll
    for (int i = 0; i < 8; i++)
#pragma unroll
        for (int j = 0; j < 4; j++) acc[i][j] = 0ull;

    float4 px[4], pw[4];
#pragma unroll
    for (int i = 0; i < 4; i++) {
        px[i] = *(const float4*)&x[(size_t)(row0 + ra[i]) * Dz + c4a[i] * 4];
        pw[i] = *(const float4*)&W[(size_t)ra[i] * Dz + c4a[i] * 4];
    }

    for (int kb = 0; kb < 32; kb++) {
#pragma unroll
        for (int i = 0; i < 4; i++) {
            int kbase = c4a[i] * 4, r = ra[i];
            xs[(kbase + 0) * 132 + r] = px[i].x; xs[(kbase + 1) * 132 + r] = px[i].y;
            xs[(kbase + 2) * 132 + r] = px[i].z; xs[(kbase + 3) * 132 + r] = px[i].w;
            ws[(kbase + 0) * 132 + r] = pw[i].x; ws[(kbase + 1) * 132 + r] = pw[i].y;
            ws[(kbase + 2) * 132 + r] = pw[i].z; ws[(kbase + 3) * 132 + r] = pw[i].w;
        }
        __syncthreads();

        if (kb < 31) {
            int koff = (kb + 1) * 32;
#pragma unroll
            for (int i = 0; i < 4; i++) {
                px[i] = *(const float4*)&x[(size_t)(row0 + ra[i]) * Dz + koff + c4a[i] * 4];
                pw[i] = *(const float4*)&W[(size_t)ra[i] * Dz + koff + c4a[i] * 4];
            }
        }

#pragma unroll 8
        for (int kk = 0; kk < 32; kk++) {
            float4 a0 = *(const float4*)&xs[kk * 132 + ty * 8];
            float4 a1 = *(const float4*)&xs[kk * 132 + ty * 8 + 4];
            ull ap[8] = { pack2(a0.x, a0.x), pack2(a0.y, a0.y),
                          pack2(a0.z, a0.z), pack2(a0.w, a0.w),
                          pack2(a1.x, a1.x), pack2(a1.y, a1.y),
                          pack2(a1.z, a1.z), pack2(a1.w, a1.w) };
            ulonglong2 b0 = *(const ulonglong2*)&ws[kk * 132 + tx * 8];
            ulonglong2 b1 = *(const ulonglong2*)&ws[kk * 132 + tx * 8 + 4];
            ull bp[4] = { b0.x, b0.y, b1.x, b1.y };
#pragma unroll
            for (int i = 0; i < 8; i++)
#pragma unroll
                for (int j = 0; j < 4; j++) fma2(acc[i][j], ap[i], bp[j]);
        }
        __syncthreads();
    }

    float bv[8];
#pragma unroll
    for (int j = 0; j < 8; j++) bv[j] = bias[tx * 8 + j];

#pragma unroll
    for (int i = 0; i < 8; i++) {
        float o[8];
#pragma unroll
        for (int j = 0; j < 4; j++) unpack2(acc[i][j], o[2 * j], o[2 * j + 1]);
        int grow = row0 + ty * 8 + i;
        float4 s0 = { o[0] + bv[0], o[1] + bv[1], o[2] + bv[2], o[3] + bv[3] };
        float4 s1 = { o[4] + bv[4], o[5] + bv[5], o[6] + bv[6], o[7] + bv[7] };
        *(float4*)&outp[(size_t)grow * KQz + tx * 8]     = s0;
        *(float4*)&outp[(size_t)grow * KQz + tx * 8 + 4] = s1;
    }
}

// ---------------------------------------------------------------------------
// top-8 insertion (sorted desc; ascending-index feed => stable ties)
// ---------------------------------------------------------------------------
__device__ __forceinline__ void topk_insert(float v, int i,
                                            float (&tv)[8], int (&ti)[8]) {
    if (v > tv[7]) {
        float pv = v; int pi = i;
#pragma unroll
        for (int p = 0; p < 8; p++) {
            if (pv > tv[p]) {
                float t = tv[p]; int u = ti[p];
                tv[p] = pv; ti[p] = pi;
                pv = t; pi = u;
            }
        }
    }
}

// ---------------------------------------------------------------------------
// Kernel 2: sim = (Q @ K^T) * scale, streaming exact top-8 + FUSED GATHER.
// CTA: 128 q-rows x 256-key chunks (8 chunks), 512 threads (16 warps),
// 8x8 thread tiles (round-12 mainloop, measured best). Scan/merge operate on
// RAW dot values (scale applied only to final outputs; scale>0 -> identical
// ranking, identical final product). After the merge, the CTA gathers its own
// 128 rows x 8 picks x 1024 floats directly from x (no separate kernel).
// ---------------------------------------------------------------------------
#define QST 132                            // Qs stride (floats)
#define KST 260                            // Ks stride (floats): 256 keys + pad
#define K2_SMEM ((128 * QST + 128 * KST) * 4)   // 67584 + 133120 = 200704 B

__global__ __launch_bounds__(512)
void sim_topk_kernel(const float* __restrict__ x,
                     float* __restrict__ out_g,
                     float* __restrict__ out_idx,
                     float* __restrict__ out_sim) {
    extern __shared__ float sm[];
    float* Qs = sm;                  // [128 d][132]  (128 rows + pad)
    float* Ks = sm + 128 * QST;      // [128 d][260]  (256 keys + pad); stage reuse

    const int tid  = threadIdx.x;
    const int tx   = tid & 31;        // 8 keys each  -> 256 keys
    const int ty   = tid >> 5;        // 8 rows each  -> 128 rows
    const int row0 = blockIdx.x * 128;
    const int b    = row0 >> 11;
    const int key0 = b * Tz;

    // load Q tile [128 rows x 128 d] transposed, conflict-free decomposition
#pragma unroll
    for (int i = 0; i < 8; i++) {
        int s  = tid + i * 512;
        int c4 = (s & 1) + (((s >> 5) & 15) << 1);    // [0,32)
        int r  = ((s >> 1) & 15) + ((s >> 9) << 4);   // [0,128)
        float4 v = *(const float4*)&g_q[(size_t)(row0 + r) * KQz + c4 * 4];
        Qs[(c4 * 4 + 0) * QST + r] = v.x; Qs[(c4 * 4 + 1) * QST + r] = v.y;
        Qs[(c4 * 4 + 2) * QST + r] = v.z; Qs[(c4 * 4 + 3) * QST + r] = v.w;
    }

    float tv[8]; int ti[8];
#pragma unroll
    for (int p = 0; p < 8; p++) { tv[p] = neg_inf(); ti[p] = 0x7fffffff; }

    const int srow  = tid >> 2;       // scan row [0,128)
    const int squad = tid & 3;        // scan quarter: keys [q*64, q*64+64)

    for (int kb = 0; kb < 8; kb++) {
        // load K chunk [256 keys x 128 d] transposed (prev scan synced)
#pragma unroll
        for (int i = 0; i < 16; i++) {
            int s  = tid + i * 512;
            int c4 = (s & 1) + (((s >> 5) & 15) << 1);    // [0,32)
            int t  = ((s >> 1) & 15) + ((s >> 9) << 4);   // [0,256)
            float4 v = *(const float4*)&g_k[(size_t)(key0 + kb * 256 + t) * KQz + c4 * 4];
            Ks[(c4 * 4 + 0) * KST + t] = v.x; Ks[(c4 * 4 + 1) * KST + t] = v.y;
            Ks[(c4 * 4 + 2) * KST + t] = v.z; Ks[(c4 * 4 + 3) * KST + t] = v.w;
        }
        __syncthreads();   // covers Qs stores on kb==0 too

        ull acc[8][4];
#pragma unroll
        for (int i = 0; i < 8; i++)
#pragma unroll
            for (int j = 0; j < 4; j++) acc[i][j] = 0ull;

#pragma unroll 8
        for (int d = 0; d < 128; d++) {
            float4 a0 = *(const float4*)&Qs[d * QST + ty * 8];
            float4 a1 = *(const float4*)&Qs[d * QST + ty * 8 + 4];
            ull ap[8] = { pack2(a0.x, a0.x), pack2(a0.y, a0.y),
                          pack2(a0.z, a0.z), pack2(a0.w, a0.w),
                          pack2(a1.x, a1.x), pack2(a1.y, a1.y),
                          pack2(a1.z, a1.z), pack2(a1.w, a1.w) };
            ulonglong2 b0 = *(const ulonglong2*)&Ks[d * KST + tx * 8];
            ulonglong2 b1 = *(const ulonglong2*)&Ks[d * KST + tx * 8 + 4];
            ull bp[4] = { b0.x, b0.y, b1.x, b1.y };
#pragma unroll
            for (int i = 0; i < 8; i++)
#pragma unroll
                for (int j = 0; j < 4; j++) fma2(acc[i][j], ap[i], bp[j]);
        }
        __syncthreads();   // all reads of Ks done before overlay

        // stage RAW sim tile into Ks region: St[row][key], stride KST
#pragma unroll
        for (int i = 0; i < 8; i++) {
            float o[8];
#pragma unroll
            for (int j = 0; j < 4; j++) unpack2(acc[i][j], o[2 * j], o[2 * j + 1]);
            int r = ty * 8 + i;
            *(float4*)&Ks[r * KST + tx * 8]     = make_float4(o[0], o[1], o[2], o[3]);
            *(float4*)&Ks[r * KST + tx * 8 + 4] = make_float4(o[4], o[5], o[6], o[7]);
        }
        __syncthreads();

        // scan: 4 threads per row, 64 keys each, group-max prefilter,
        // ascending index feed (stable ties)
        {
            const float* sp = &Ks[srow * KST + squad * 64];
            int kbase = kb * 256 + squad * 64;
#pragma unroll
            for (int q = 0; q < 16; q++) {
                float4 v = *(const float4*)&sp[q * 4];
                float m = fmaxf(fmaxf(v.x, v.y), fmaxf(v.z, v.w));
                if (m > tv[7]) {
                    topk_insert(v.x, kbase + q * 4 + 0, tv, ti);
                    topk_insert(v.y, kbase + q * 4 + 1, tv, ti);
                    topk_insert(v.z, kbase + q * 4 + 2, tv, ti);
                    topk_insert(v.w, kbase + q * 4 + 3, tv, ti);
                }
            }
        }
        __syncthreads();   // scan done before next chunk overwrites Ks
    }

    // 4-way merge of per-quarter sorted lists (dump into Qs region, now free)
    float* sv = Qs;                         // [128][4][8] values
    int*   si = (int*)(Qs + 4096);          // [128][4][8] indices
    int*   mi = (int*)(Qs + 8192);          // [128][8] merged indices (for gather)
#pragma unroll
    for (int p = 0; p < 8; p++) {
        sv[(srow * 4 + squad) * 8 + p] = tv[p];
        si[(srow * 4 + squad) * 8 + p] = ti[p];
    }
    __syncthreads();

    if (tid < 128) {
        const float* v4 = &sv[tid * 32];
        const int*   i4 = &si[tid * 32];
        int p0 = 0, p1 = 0, p2 = 0, p3 = 0;
        int grow = row0 + tid;
#pragma unroll
        for (int r = 0; r < 8; r++) {
            float b0 = (p0 < 8) ? v4[p0]      : neg_inf();
            float b1 = (p1 < 8) ? v4[8 + p1]  : neg_inf();
            float b2 = (p2 < 8) ? v4[16 + p2] : neg_inf();
            float b3 = (p3 < 8) ? v4[24 + p3] : neg_inf();
            int   j0 = (p0 < 8) ? i4[p0]      : 0x7fffffff;
            int   j1 = (p1 < 8) ? i4[8 + p1]  : 0x7fffffff;
            int   j2 = (p2 < 8) ? i4[16 + p2] : 0x7fffffff;
            int   j3 = (p3 < 8) ? i4[24 + p3] : 0x7fffffff;
            // pick best of 4 (value desc, index asc on ties)
            float bv = b0; int bj = j0; int sel = 0;
            if (b1 > bv || (b1 == bv && j1 < bj)) { bv = b1; bj = j1; sel = 1; }
            if (b2 > bv || (b2 == bv && j2 < bj)) { bv = b2; bj = j2; sel = 2; }
            if (b3 > bv || (b3 == bv && j3 < bj)) { bv = b3; bj = j3; sel = 3; }
            if      (sel == 0) p0++;
            else if (sel == 1) p1++;
            else if (sel == 2) p2++;
            else               p3++;
            out_idx[(size_t)grow * TOPK + r] = (float)bj;
            out_sim[(size_t)grow * TOPK + r] = bv * SIM_SCALE;
            mi[tid * TOPK + r] = bj;
        }
    }
    __syncthreads();

    // fused gather: 1024 jobs (row, pick) for this CTA's 128 rows; warp per
    // job group. job j -> row j>>3, pick j&7. Each warp copies 4 KB.
    {
        const int wid  = tid >> 5;
        const int lane = tid & 31;
        const float* xb = x + (size_t)key0 * Dz;
#pragma unroll 1
        for (int j = wid; j < 128 * TOPK; j += 16) {
            int idx = mi[j];
            const float4* src = (const float4*)(xb + (size_t)idx * Dz);
            float4* dst = (float4*)(out_g + ((size_t)(row0) * TOPK + j) * Dz);
#pragma unroll
            for (int q = 0; q < 8; q++)
                __stcs(&dst[q * 32 + lane], __ldg(&src[q * 32 + lane]));
        }
    }
}

// ---------------------------------------------------------------------------
extern "C" void kernel_launch(void* const* d_in, const int* in_sizes, int n_in,
                              void* d_out, int out_size) {
    const float* x  = (const float*)d_in[0];
    const float* Wq = (const float*)d_in[1];
    const float* bq = (const float*)d_in[2];
    const float* Wk = (const float*)d_in[3];
    const float* bk = (const float*)d_in[4];

    float* out      = (float*)d_out;
    float* out_g    = out;                                   // [B,T,8,D]
    float* out_idx  = out + (size_t)BT * TOPK * Dz;          // [B,T,8] as float
    float* out_sim  = out_idx + (size_t)BT * TOPK;           // [B,T,8]

    cudaFuncSetAttribute(sim_topk_kernel,
                         cudaFuncAttributeMaxDynamicSharedMemorySize, K2_SMEM);

    qk2_kernel<<<dim3(BT / 128, 2), 256>>>(x, Wq, bq, Wk, bk);
    sim_topk_kernel<<<BT / 128, 512, K2_SMEM>>>(x, out_g, out_idx, out_sim);
}

// round 15
// speedup vs baseline: 1.1882x; 1.0352x over previous
#include <cuda_runtime.h>
#include <cuda_bf16.h>
#include <cstdint>
#include <cstddef>

// Problem constants: B=8, T=2048, D=1024, KQ=128, topk=8
#define Bz   8
#define Tz   2048
#define Dz   1024
#define KQz  128
#define TOPK 8
#define BT   (Bz * Tz)          // 16384 rows
#define SIM_SCALE 0.08838834764831843f   // 1/sqrt(128)

typedef unsigned long long ull;

// Scratch (device globals: no allocation allowed in kernel_launch)
__device__ float g_q[BT * KQz];      // 8 MB
__device__ float g_k[BT * KQz];      // 8 MB
__device__ int   g_idx[BT * TOPK];   // routed indices for gather

// ---------------------------------------------------------------------------
// f32x2 packed-FMA helpers (FFMA2: 2 fp32 FMAs per instruction)
// ---------------------------------------------------------------------------
__device__ __forceinline__ ull pack2(float a, float b) {
    ull r;
    asm("mov.b64 %0, {%1, %2};" : "=l"(r)
        : "r"(__float_as_uint(a)), "r"(__float_as_uint(b)));
    return r;
}
__device__ __forceinline__ void unpack2(ull v, float& a, float& b) {
    unsigned int lo, hi;
    asm("mov.b64 {%0, %1}, %2;" : "=r"(lo), "=r"(hi) : "l"(v));
    a = __uint_as_float(lo);
    b = __uint_as_float(hi);
}
__device__ __forceinline__ void fma2(ull& d, ull a, ull b) {
    asm("fma.rn.f32x2 %0, %1, %2, %0;" : "+l"(d) : "l"(a), "l"(b));
}
__device__ __forceinline__ float neg_inf() { return __int_as_float(0xff800000); }

// ---------------------------------------------------------------------------
// Kernel 1 (UNCHANGED — ~measured fp32 roofline): projection GEMM.
// blockIdx.y = 0 -> Q (Wq,bq), 1 -> K (Wk,bk). 128x128 CTA tile, 8x8/thread.
// ---------------------------------------------------------------------------
__global__ __launch_bounds__(256)
void qk2_kernel(const float* __restrict__ x,
                const float* __restrict__ Wq, const float* __restrict__ bq,
                const float* __restrict__ Wk, const float* __restrict__ bk) {
    __shared__ float xs[32 * 132];   // [k][row], stride 132
    __shared__ float ws[32 * 132];   // [k][col], stride 132

    const float* W    = blockIdx.y ? Wk : Wq;
    const float* bias = blockIdx.y ? bk : bq;
    float* outp       = blockIdx.y ? g_k : g_q;

    const int tid  = threadIdx.x;
    const int tx   = tid & 15;
    const int ty   = tid >> 4;
    const int row0 = blockIdx.x * 128;

    int c4a[4], ra[4];
#pragma unroll
    for (int i = 0; i < 4; i++) {
        int s = tid + i * 256;
        c4a[i] = (s & 1) + (((s >> 5) & 3) << 1);
        ra[i]  = ((s >> 1) & 15) + ((s >> 7) << 4);
    }

    ull acc[8][4];
#pragma unroll
    for (int i = 0; i < 8; i++)
#pragma unroll
        for (int j = 0; j < 4; j++) acc[i][j] = 0ull;

    float4 px[4], pw[4];
#pragma unroll
    for (int i = 0; i < 4; i++) {
        px[i] = *(const float4*)&x[(size_t)(row0 + ra[i]) * Dz + c4a[i] * 4];
        pw[i] = *(const float4*)&W[(size_t)ra[i] * Dz + c4a[i] * 4];
    }

    for (int kb = 0; kb < 32; kb++) {
#pragma unroll
        for (int i = 0; i < 4; i++) {
            int kbase = c4a[i] * 4, r = ra[i];
            xs[(kbase + 0) * 132 + r] = px[i].x; xs[(kbase + 1) * 132 + r] = px[i].y;
            xs[(kbase + 2) * 132 + r] = px[i].z; xs[(kbase + 3) * 132 + r] = px[i].w;
            ws[(kbase + 0) * 132 + r] = pw[i].x; ws[(kbase + 1) * 132 + r] = pw[i].y;
            ws[(kbase + 2) * 132 + r] = pw[i].z; ws[(kbase + 3) * 132 + r] = pw[i].w;
        }
        __syncthreads();

        if (kb < 31) {
            int koff = (kb + 1) * 32;
#pragma unroll
            for (int i = 0; i < 4; i++) {
                px[i] = *(const float4*)&x[(size_t)(row0 + ra[i]) * Dz + koff + c4a[i] * 4];
                pw[i] = *(const float4*)&W[(size_t)ra[i] * Dz + koff + c4a[i] * 4];
            }
        }

#pragma unroll 8
        for (int kk = 0; kk < 32; kk++) {
            float4 a0 = *(const float4*)&xs[kk * 132 + ty * 8];
            float4 a1 = *(const float4*)&xs[kk * 132 + ty * 8 + 4];
            ull ap[8] = { pack2(a0.x, a0.x), pack2(a0.y, a0.y),
                          pack2(a0.z, a0.z), pack2(a0.w, a0.w),
                          pack2(a1.x, a1.x), pack2(a1.y, a1.y),
                          pack2(a1.z, a1.z), pack2(a1.w, a1.w) };
            ulonglong2 b0 = *(const ulonglong2*)&ws[kk * 132 + tx * 8];
            ulonglong2 b1 = *(const ulonglong2*)&ws[kk * 132 + tx * 8 + 4];
            ull bp[4] = { b0.x, b0.y, b1.x, b1.y };
#pragma unroll
            for (int i = 0; i < 8; i++)
#pragma unroll
                for (int j = 0; j < 4; j++) fma2(acc[i][j], ap[i], bp[j]);
        }
        __syncthreads();
    }

    float bv[8];
#pragma unroll
    for (int j = 0; j < 8; j++) bv[j] = bias[tx * 8 + j];

#pragma unroll
    for (int i = 0; i < 8; i++) {
        float o[8];
#pragma unroll
        for (int j = 0; j < 4; j++) unpack2(acc[i][j], o[2 * j], o[2 * j + 1]);
        int grow = row0 + ty * 8 + i;
        float4 s0 = { o[0] + bv[0], o[1] + bv[1], o[2] + bv[2], o[3] + bv[3] };
        float4 s1 = { o[4] + bv[4], o[5] + bv[5], o[6] + bv[6], o[7] + bv[7] };
        *(float4*)&outp[(size_t)grow * KQz + tx * 8]     = s0;
        *(float4*)&outp[(size_t)grow * KQz + tx * 8 + 4] = s1;
    }
}

// ---------------------------------------------------------------------------
// top-8 insertion (sorted desc; ascending-index feed => stable ties)
// ---------------------------------------------------------------------------
__device__ __forceinline__ void topk_insert(float v, int i,
                                            float (&tv)[8], int (&ti)[8]) {
    if (v > tv[7]) {
        float pv = v; int pi = i;
#pragma unroll
        for (int p = 0; p < 8; p++) {
            if (pv > tv[p]) {
                float t = tv[p]; int u = ti[p];
                tv[p] = pv; ti[p] = pi;
                pv = t; pi = u;
            }
        }
    }
}

// ---------------------------------------------------------------------------
// Kernel 2: sim = (Q @ K^T), streaming exact top-8 on RAW dot values.
// Grid: 18 CTAs per batch x 8 batches = 144 (fills 144/148 SMs, 1 wave).
// CTA: 120 q-rows (rows clamped in ragged last CTA) x 256-key chunks
// (8 chunks), 480 threads (15 warps), 8x8 thread tiles (measured-best
// mainloop). Per chunk: GEMM -> stage raw tile into K buf -> 4 threads/row
// scan quarters with prefilter -> 4-way smem merge at end (scale on output).
// ---------------------------------------------------------------------------
#define ROWS 120                           // rows per CTA tile
#define CPB  18                            // CTAs per batch
#define NTH  480
#define QST 124                            // Qs stride (120 rows + pad)
#define KST 260                            // Ks stride (256 keys + pad)
#define K2_SMEM ((128 * QST + 128 * KST) * 4)   // 63488 + 133120 = 196608 B

__global__ __launch_bounds__(NTH)
void sim_topk_kernel(float* __restrict__ out_idx, float* __restrict__ out_sim) {
    extern __shared__ float sm[];
    float* Qs = sm;                  // [128 d][124]  (120 rows + pad)
    float* Ks = sm + 128 * QST;      // [128 d][260]  (256 keys + pad); stage reuse

    const int tid  = threadIdx.x;
    const int tx   = tid & 31;        // 8 keys each  -> 256 keys
    const int ty   = tid >> 5;        // 8 rows each  -> 120 rows (ty 0..14)
    const int lane = tid & 31;
    const int warp = tid >> 5;
    const int batch = blockIdx.x / CPB;
    const int cb    = blockIdx.x - batch * CPB;     // CTA index in batch
    const int rb0   = cb * ROWS;                    // first row in batch
    const int row0  = batch * Tz + rb0;             // global row base
    const int key0  = batch * Tz;

    // load Q tile [120 rows x 128 d] transposed; ragged rows clamped.
    // mapping: m = 8*(m>>3)+(m&7); t = (lane>>2)+8*(m>>3), c4 = (lane&3)+4*(m&7)
#pragma unroll
    for (int i = 0; i < 8; i++) {
        int m  = 15 * i + warp;               // [0,120)
        int t  = (lane >> 2) + 8 * (m >> 3);  // tile row [0,120)
        int c4 = (lane & 3) + 4 * (m & 7);    // dim group [0,32)
        int rl = min(rb0 + t, Tz - 1);        // clamp within batch
        float4 v = *(const float4*)&g_q[(size_t)(batch * Tz + rl) * KQz + c4 * 4];
        Qs[(c4 * 4 + 0) * QST + t] = v.x; Qs[(c4 * 4 + 1) * QST + t] = v.y;
        Qs[(c4 * 4 + 2) * QST + t] = v.z; Qs[(c4 * 4 + 3) * QST + t] = v.w;
    }

    float tv[8]; int ti[8];
#pragma unroll
    for (int p = 0; p < 8; p++) { tv[p] = neg_inf(); ti[p] = 0x7fffffff; }

    const int srow  = tid >> 2;       // scan row [0,120)
    const int squad = tid & 3;        // scan quarter: keys [q*64, q*64+64)

    for (int kb = 0; kb < 8; kb++) {
        // load K chunk [256 keys x 128 d] transposed, conflict-free:
        // m = 15*i + warp < 256; t = (lane>>1)+16*(m>>4); c4 = (lane&1)+2*(m&15)
#pragma unroll
        for (int i = 0; i < 18; i++) {
            int m = 15 * i + warp;
            if (m < 256) {
                int t  = (lane >> 1) + 16 * (m >> 4);   // key [0,256)
                int c4 = (lane & 1) + 2 * (m & 15);     // dim group [0,32)
                float4 v = *(const float4*)&g_k[(size_t)(key0 + kb * 256 + t) * KQz + c4 * 4];
                Ks[(c4 * 4 + 0) * KST + t] = v.x; Ks[(c4 * 4 + 1) * KST + t] = v.y;
                Ks[(c4 * 4 + 2) * KST + t] = v.z; Ks[(c4 * 4 + 3) * KST + t] = v.w;
            }
        }
        __syncthreads();   // covers Qs stores on kb==0 too

        ull acc[8][4];
#pragma unroll
        for (int i = 0; i < 8; i++)
#pragma unroll
            for (int j = 0; j < 4; j++) acc[i][j] = 0ull;

#pragma unroll 8
        for (int d = 0; d < 128; d++) {
            float4 a0 = *(const float4*)&Qs[d * QST + ty * 8];
            float4 a1 = *(const float4*)&Qs[d * QST + ty * 8 + 4];
            ull ap[8] = { pack2(a0.x, a0.x), pack2(a0.y, a0.y),
                          pack2(a0.z, a0.z), pack2(a0.w, a0.w),
                          pack2(a1.x, a1.x), pack2(a1.y, a1.y),
                          pack2(a1.z, a1.z), pack2(a1.w, a1.w) };
            ulonglong2 b0 = *(const ulonglong2*)&Ks[d * KST + tx * 8];
            ulonglong2 b1 = *(const ulonglong2*)&Ks[d * KST + tx * 8 + 4];
            ull bp[4] = { b0.x, b0.y, b1.x, b1.y };
#pragma unroll
            for (int i = 0; i < 8; i++)
#pragma unroll
                for (int j = 0; j < 4; j++) fma2(acc[i][j], ap[i], bp[j]);
        }
        __syncthreads();   // all reads of Ks done before overlay

        // stage RAW sim tile into Ks region: St[row][key], stride KST
#pragma unroll
        for (int i = 0; i < 8; i++) {
            float o[8];
#pragma unroll
            for (int j = 0; j < 4; j++) unpack2(acc[i][j], o[2 * j], o[2 * j + 1]);
            int r = ty * 8 + i;
            *(float4*)&Ks[r * KST + tx * 8]     = make_float4(o[0], o[1], o[2], o[3]);
            *(float4*)&Ks[r * KST + tx * 8 + 4] = make_float4(o[4], o[5], o[6], o[7]);
        }
        __syncthreads();

        // scan: 4 threads per row, 64 keys each, group-max prefilter,
        // ascending index feed (stable ties)
        {
            const float* sp = &Ks[srow * KST + squad * 64];
            int kbase = kb * 256 + squad * 64;
#pragma unroll
            for (int q = 0; q < 16; q++) {
                float4 v = *(const float4*)&sp[q * 4];
                float m = fmaxf(fmaxf(v.x, v.y), fmaxf(v.z, v.w));
                if (m > tv[7]) {
                    topk_insert(v.x, kbase + q * 4 + 0, tv, ti);
                    topk_insert(v.y, kbase + q * 4 + 1, tv, ti);
                    topk_insert(v.z, kbase + q * 4 + 2, tv, ti);
                    topk_insert(v.w, kbase + q * 4 + 3, tv, ti);
                }
            }
        }
        __syncthreads();   // scan done before next chunk overwrites Ks
    }

    // 4-way merge of per-quarter sorted lists (dump into Qs region, now free)
    float* sv = Qs;                         // [120][4][8] values
    int*   si = (int*)(Qs + 3840);          // [120][4][8] indices
#pragma unroll
    for (int p = 0; p < 8; p++) {
        sv[(srow * 4 + squad) * 8 + p] = tv[p];
        si[(srow * 4 + squad) * 8 + p] = ti[p];
    }
    __syncthreads();

    if (tid < ROWS && rb0 + tid < Tz) {     // skip padded/duplicate rows
        const float* v4 = &sv[tid * 32];
        const int*   i4 = &si[tid * 32];
        int p0 = 0, p1 = 0, p2 = 0, p3 = 0;
        int grow = row0 + tid;
#pragma unroll
        for (int r = 0; r < 8; r++) {
            float b0 = (p0 < 8) ? v4[p0]      : neg_inf();
            float b1 = (p1 < 8) ? v4[8 + p1]  : neg_inf();
            float b2 = (p2 < 8) ? v4[16 + p2] : neg_inf();
            float b3 = (p3 < 8) ? v4[24 + p3] : neg_inf();
            int   j0 = (p0 < 8) ? i4[p0]      : 0x7fffffff;
            int   j1 = (p1 < 8) ? i4[8 + p1]  : 0x7fffffff;
            int   j2 = (p2 < 8) ? i4[16 + p2] : 0x7fffffff;
            int   j3 = (p3 < 8) ? i4[24 + p3] : 0x7fffffff;
            // pick best of 4 (value desc, index asc on ties)
            float bv = b0; int bj = j0; int sel = 0;
            if (b1 > bv || (b1 == bv && j1 < bj)) { bv = b1; bj = j1; sel = 1; }
            if (b2 > bv || (b2 == bv && j2 < bj)) { bv = b2; bj = j2; sel = 2; }
            if (b3 > bv || (b3 == bv && j3 < bj)) { bv = b3; bj = j3; sel = 3; }
            if      (sel == 0) p0++;
            else if (sel == 1) p1++;
            else if (sel == 2) p2++;
            else               p3++;
            out_idx[(size_t)grow * TOPK + r] = (float)bj;
            out_sim[(size_t)grow * TOPK + r] = bv * SIM_SCALE;
            g_idx [(size_t)grow * TOPK + r] = bj;
        }
    }
}

// ---------------------------------------------------------------------------
// Kernel 3: gather routed tokens. One CTA per query row; warp w copies pick w.
// ---------------------------------------------------------------------------
__global__ __launch_bounds__(256)
void gather_kernel(const float* __restrict__ x, float* __restrict__ out) {
    const int row  = blockIdx.x;
    const int w    = threadIdx.x >> 5;
    const int lane = threadIdx.x & 31;
    const int job  = row * TOPK + w;
    const int b    = row >> 11;
    const int idx  = g_idx[job];
    const float4* src = (const float4*)(x + (size_t)(b * Tz + idx) * Dz);
    float4* dst = (float4*)(out + (size_t)job * Dz);
#pragma unroll
    for (int j = 0; j < 8; j++) __stcs(&dst[j * 32 + lane], src[j * 32 + lane]);
}

// ---------------------------------------------------------------------------
extern "C" void kernel_launch(void* const* d_in, const int* in_sizes, int n_in,
                              void* d_out, int out_size) {
    const float* x  = (const float*)d_in[0];
    const float* Wq = (const float*)d_in[1];
    const float* bq = (const float*)d_in[2];
    const float* Wk = (const float*)d_in[3];
    const float* bk = (const float*)d_in[4];

    float* out      = (float*)d_out;
    float* out_g    = out;                                   // [B,T,8,D]
    float* out_idx  = out + (size_t)BT * TOPK * Dz;          // [B,T,8] as float
    float* out_sim  = out_idx + (size_t)BT * TOPK;           // [B,T,8]

    cudaFuncSetAttribute(sim_topk_kernel,
                         cudaFuncAttributeMaxDynamicSharedMemorySize, K2_SMEM);

    qk2_kernel<<<dim3(BT / 128, 2), 256>>>(x, Wq, bq, Wk, bk);
    sim_topk_kernel<<<Bz * CPB, NTH, K2_SMEM>>>(out_idx, out_sim);
    gather_kernel<<<BT, 256>>>(x, out_g);
}